// round 14
// baseline (speedup 1.0000x reference)
#include <cuda_runtime.h>
#include <cuda_bf16.h>
#include <math.h>
#include <stdint.h>

// Problem constants
#define Bn  32
#define Cc  80
#define TXn 512
#define TYn 2048
#define K2  160          // stacked K: [scale(80); mean*scale(80)]
#define NEGV (-1e9f)
#define LOG2PI 1.8378770664093453f
#define NYT (TYn/128)    // 16 y-tiles of 128 columns

// Output layout (flat f32, reference return order)
#define Z_OFF        0
#define YMEAN_OFF    (Bn*Cc*TYn)
#define YLOG_OFF     (2*Bn*Cc*TYn)
#define ATTN_OFF     (3*Bn*Cc*TYn)
#define ODUR_OFF     (ATTN_OFF + Bn*TYn*TXn)
#define OADUR_OFF    (ODUR_OFF + Bn*TXn)

// tail kernel block ranges (256 threads each)
#define TB_ATTN   (Bn*TYn/2)                  // 32768 blocks, 2 attn rows each
#define TB_GATH   (Bn*Cc*TYn/256)             // 20480 blocks
#define TB_DUR    (Bn*TXn/256)                // 64 blocks

// -------------------- scratch (__device__ globals) --------------------------
__device__ float    g_W[Bn*K2*TXn];              // [b][k][x]
__device__ float    g_Z[Bn*K2*TYn];              // [b][k][y]
__device__ float    g_rowA[Bn*TXn];              // logp1+logp4 per (b,x)
__device__ float    g_logpT[(size_t)Bn*TYn*TXn]; // 134 MB [b][y][x]
__device__ unsigned g_dbits[(size_t)Bn*TYn*16];  // dir bits, 32 per warp-word
__device__ int      g_xy[Bn*TYn];                // alignment index per (b,y)
__device__ int      g_prog[Bn*NYT];              // gemm tiles done per (b,ytile)

// -------------------- K1: per-(b,x) prep -------------------------------------
__global__ void prepx_kernel(const float* __restrict__ om,
                             const float* __restrict__ ols,
                             const float* __restrict__ odur,
                             float* __restrict__ out)
{
    int i = blockIdx.x * blockDim.x + threadIdx.x;
    if (i >= Bn*TXn) return;
    if (i < Bn*NYT) g_prog[i] = 0;     // reset producer counters each launch
    int b = i / TXn, x = i % TXn;
    const float* omb = om  + (size_t)b*Cc*TXn + x;
    const float* olb = ols + (size_t)b*Cc*TXn + x;
    float* wS = g_W + (size_t)b*K2*TXn + x;
    float sa = 0.f;
    #pragma unroll 4
    for (int c = 0; c < Cc; c++) {
        float l  = olb[(size_t)c*TXn];
        float sc = expf(-2.f*l);
        float m  = omb[(size_t)c*TXn];
        wS[(size_t)c*TXn]        = sc;
        wS[(size_t)(Cc+c)*TXn]   = m*sc;
        sa += -0.5f*LOG2PI - l - 0.5f*m*m*sc;
    }
    g_rowA[i] = sa;
    out[ODUR_OFF + i] = odur[i];
}

// -------------------- K2: z masking + Z matrix --------------------------------
__global__ void prepz_kernel(const float* __restrict__ z,
                             const int* __restrict__ yl,
                             float* __restrict__ out)
{
    int i = blockIdx.x * blockDim.x + threadIdx.x;
    if (i >= Bn*Cc*TYn) return;
    int b = i / (Cc*TYn);
    int r = i % (Cc*TYn);
    int c = r / TYn;
    int y = r % TYn;
    float zv = z[i];
    if (y >= yl[b]) zv = 0.f;
    out[Z_OFF + i] = zv;
    size_t zb = (size_t)b*K2*TYn;
    g_Z[zb + (size_t)c*TYn + y]      = -0.5f*zv*zv;
    g_Z[zb + (size_t)(Cc+c)*TYn + y] = zv;
}

// -------------------- K3: fused gemm (producers) + forward DP (consumers) ------
__global__ void __launch_bounds__(512)
fused_kernel(const int* __restrict__ xl, const int* __restrict__ yl)
{
    __shared__ float smem[2*16*128];       // gemm tiles (fwd uses tiny slice)
    int tid = threadIdx.x;

    if (blockIdx.x >= 32) {
        // ---------------- GEMM producer role (verbatim R12) ----------------
        int gid = blockIdx.x - 32;
        int yt  = gid >> 7;                // 0..15 (slab-major)
        int rem = gid & 127;
        int b   = rem >> 2;
        int x0  = (rem & 3) * 128;
        int y0  = yt * 128;
        int xlen = xl[b], ylen = yl[b];

        bool skip = (x0 >= xlen) || (y0 >= ylen) ||
                    (x0 > y0 + 127) || (x0 + 127 < y0 - (ylen - xlen));
        if (!skip) {
            float (*zs)[128] = (float (*)[128])smem;
            float (*ws)[128] = (float (*)[128])(smem + 16*128);
            int lrow = tid >> 5;           // 0..15
            int lcol = (tid & 31) << 2;    // 0..124
            int ty   = tid >> 4;           // 0..31 (4 y each)
            int tx   = tid & 15;           // 0..15 (8 x each)

            const float* Zb = g_Z + (size_t)b*K2*TYn;
            const float* Wb = g_W + (size_t)b*K2*TXn;

            float acc[4][8] = {};
            for (int k0 = 0; k0 < K2; k0 += 16) {
                *(float4*)&zs[lrow][lcol] =
                    *(const float4*)&Zb[(size_t)(k0+lrow)*TYn + y0 + lcol];
                *(float4*)&ws[lrow][lcol] =
                    *(const float4*)&Wb[(size_t)(k0+lrow)*TXn + x0 + lcol];
                __syncthreads();
                #pragma unroll
                for (int k = 0; k < 16; k++) {
                    float4 zf = *(float4*)&zs[k][ty<<2];
                    float4 w0 = *(float4*)&ws[k][tx<<3];
                    float4 w1 = *(float4*)&ws[k][(tx<<3)+4];
                    float za[4] = {zf.x, zf.y, zf.z, zf.w};
                    float wa[8] = {w0.x,w0.y,w0.z,w0.w,w1.x,w1.y,w1.z,w1.w};
                    #pragma unroll
                    for (int i = 0; i < 4; i++)
                        #pragma unroll
                        for (int j = 0; j < 8; j++)
                            acc[i][j] += za[i]*wa[j];
                }
                __syncthreads();
            }

            float ra[8];
            #pragma unroll
            for (int j = 0; j < 8; j++)
                ra[j] = g_rowA[b*TXn + x0 + (tx<<3) + j];

            #pragma unroll
            for (int i = 0; i < 4; i++) {
                int y = y0 + (ty<<2) + i;
                float* op = g_logpT + ((size_t)b*TYn + y)*TXn + x0 + (tx<<3);
                float4 o0, o1;
                float* p0 = (float*)&o0; float* p1 = (float*)&o1;
                bool yok = (y < ylen);
                #pragma unroll
                for (int j = 0; j < 4; j++) {
                    int xa = x0 + (tx<<3) + j;
                    int xb = xa + 4;
                    p0[j] = (yok && xa < xlen) ? (acc[i][j]   + ra[j])   : 0.f;
                    p1[j] = (yok && xb < xlen) ? (acc[i][j+4] + ra[j+4]) : 0.f;
                }
                *(float4*)op       = o0;
                *(float4*)(op + 4) = o1;
            }
        }
        __threadfence();
        __syncthreads();
        if (tid == 0) atomicAdd(&g_prog[b*NYT + yt], 1);
        return;
    }

    // ---------------- forward-DP consumer role ----------------
    int b    = blockIdx.x;
    int x    = tid;
    int w    = x >> 5, lane = x & 31;
    int xlen = xl[b], ylen = yl[b];

    float* sb = smem;                     // [2][16] boundary values

    unsigned force;
    {
        int rel = xlen - (w << 5);
        if (rel <= 0)      force = 0xFFFFFFFFu;
        else if (rel < 32) force = 0xFFFFFFFFu << rel;
        else               force = 0u;
    }

    float v = 0.f;
    if (lane == 31) { sb[0*16 + w] = 0.f; sb[1*16 + w] = 0.f; }

    const float* base  = g_logpT + (size_t)b*TYn*TXn + x;
    unsigned*    dbase = g_dbits + (size_t)b*TYn*16 + w;

    int last_yt = (ylen - 1) >> 7;

    auto gate = [&](int yt) {
        if (yt > last_yt) yt = last_yt;
        if (tid == 0) {
            const int* p = &g_prog[b*NYT + yt];
            int pv;
            do {
                asm volatile("ld.acquire.gpu.s32 %0, [%1];"
                             : "=r"(pv) : "l"(p) : "memory");
                if (pv < 4) __nanosleep(256);
            } while (pv < 4);
        }
        __syncthreads();
    };

    gate(0);

    const int PF = 8;
    float c[PF];
    #pragma unroll
    for (int d = 0; d < PF; d++)
        c[d] = (d < ylen) ? base[(size_t)d*TXn] : 0.f;
    __syncthreads();

    for (int j0 = 0; j0 < ylen; j0 += PF) {
        if ((j0 & 127) == 120) gate((j0 >> 7) + 1);

        float cn[PF];
        if (j0 < TXn) {
            // ---- ramp region: x > j masking required ----
            #pragma unroll
            for (int d = 0; d < PF; d++) {
                int j = j0 + d;
                if (j < ylen) {                      // uniform per block
                    int jp = j + PF;
                    cn[d] = (jp < ylen) ? base[(size_t)jp*TXn] : 0.f;

                    float left = __shfl_up_sync(0xFFFFFFFFu, v, 1);
                    if (lane == 0) left = (w == 0) ? NEGV : sb[(j & 1)*16 + (w - 1)];

                    bool  di = v >= left;
                    float nv = (di ? v : left) + c[d];
                    if (x > j) nv = NEGV;

                    unsigned bits = __ballot_sync(0xFFFFFFFFu, di) | force;
                    if (lane == 0) dbase[(size_t)j*16] = bits;

                    v = nv;
                    if (lane == 31) sb[((j + 1) & 1)*16 + w] = nv;
                    __syncthreads();
                }
            }
        } else {
            // ---- steady region: j >= 512 > max x, mask provably dead ----
            #pragma unroll
            for (int d = 0; d < PF; d++) {
                int j = j0 + d;
                if (j < ylen) {                      // uniform per block
                    int jp = j + PF;
                    cn[d] = (jp < ylen) ? base[(size_t)jp*TXn] : 0.f;

                    float left = __shfl_up_sync(0xFFFFFFFFu, v, 1);
                    if (lane == 0) left = (w == 0) ? NEGV : sb[(j & 1)*16 + (w - 1)];

                    bool  di = v >= left;
                    float nv = (di ? v : left) + c[d];

                    unsigned bits = __ballot_sync(0xFFFFFFFFu, di) | force;
                    if (lane == 0) dbase[(size_t)j*16] = bits;

                    v = nv;
                    if (lane == 31) sb[((j + 1) & 1)*16 + w] = nv;
                    __syncthreads();
                }
            }
        }
        #pragma unroll
        for (int d = 0; d < PF; d++) c[d] = cn[d];
    }
}

// -------------------- K4: backtrack (1 warp per batch, minimal chain) ----------
// Lanes preload the two candidate words per column; per step, both are
// broadcast (walk-independent operands pipeline ahead), selection happens
// after; lane s keeps its own column's idx; coalesced store per 32-block.
// Duration counts are NOT computed here (derived in tail via binary search).
__global__ void __launch_bounds__(32)
bwd_kernel(const int* __restrict__ xl, const int* __restrict__ yl)
{
    int b = blockIdx.x, lane = threadIdx.x;
    int xlen = xl[b], ylen = yl[b];

    for (int j = ylen + lane; j < TYn; j += 32) g_xy[b*TYn + j] = 0;

    int idx = xlen - 1;
    for (int jhi = ylen - 1; jhi >= 0; jhi -= 32) {
        int steps = min(32, jhi + 1);
        int j = jhi - lane;
        int w0 = idx >> 5;                 // block-entry word; spans {w0, w0-1}
        unsigned d0 = 0xFFFFFFFFu, d1 = 0xFFFFFFFFu;
        if (lane < steps) {
            const unsigned* p = g_dbits + ((size_t)b*TYn + j)*16;
            d0 = p[w0];
            if (w0 >= 1) d1 = p[w0-1];
        }
        int myidx = 0;
        #pragma unroll 4
        for (int s = 0; s < steps; s++) {
            unsigned e0 = __shfl_sync(0xFFFFFFFFu, d0, s);
            unsigned e1 = __shfl_sync(0xFFFFFFFFu, d1, s);
            if (lane == s) myidx = idx;
            unsigned word = ((idx >> 5) == w0) ? e0 : e1;
            idx += (int)((word >> (idx & 31)) & 1u) - 1;
        }
        if (lane < steps) g_xy[b*TYn + jhi - lane] = myidx;
    }
}

// -------------------- K5: merged tail (attn + gathers + durations) -------------
__global__ void __launch_bounds__(256)
tail_kernel(const float* __restrict__ om,
            const float* __restrict__ ols,
            const int* __restrict__ xlv,
            const int* __restrict__ ylv,
            float* __restrict__ out)
{
    int blk = blockIdx.x;
    int tid = threadIdx.x;

    if (blk < TB_ATTN) {
        // attn_out: 2 rows per block, 128 threads each, float4 stores
        int r = (blk << 1) + (tid >> 7);      // row id in [0, Bn*TYn)
        int b = r >> 11;                      // TYn = 2048
        int y = r & (TYn - 1);
        int t = tid & 127;
        int xi = (y < ylv[b]) ? g_xy[b*TYn + y] : -1;
        int x4 = t << 2;
        float4 v = make_float4(0.f, 0.f, 0.f, 0.f);
        if (xi >= x4 && xi < x4 + 4) ((float*)&v)[xi - x4] = 1.0f;
        *(float4*)&out[ATTN_OFF + (size_t)r*TXn + x4] = v;
    } else if (blk < TB_ATTN + TB_GATH) {
        // y_mean / y_log_scale gathers
        int i = (blk - TB_ATTN)*256 + tid;
        int b = i / (Cc*TYn);
        int r = i % (Cc*TYn);
        int c = r / TYn;
        int y = r % TYn;
        float m = 0.f, s = 0.f;
        if (y < ylv[b]) {
            int x = g_xy[b*TYn + y];
            m = om [(size_t)(b*Cc + c)*TXn + x];
            s = ols[(size_t)(b*Cc + c)*TXn + x];
        }
        out[YMEAN_OFF + i] = m;
        out[YLOG_OFF  + i] = s;
    } else {
        // o_attn_dur: count via binary search over monotone xy[b][0..ylen)
        int i = (blk - TB_ATTN - TB_GATH)*256 + tid;
        int b = i / TXn, x = i % TXn;
        int ylen = ylv[b];
        const int* xy = g_xy + b*TYn;
        int lo = 0, hi = ylen;
        while (lo < hi) { int mid = (lo + hi) >> 1;
                          if (xy[mid] < x) lo = mid + 1; else hi = mid; }
        int lb = lo;
        lo = 0; hi = ylen;
        while (lo < hi) { int mid = (lo + hi) >> 1;
                          if (xy[mid] <= x) lo = mid + 1; else hi = mid; }
        int cnt = lo - lb;
        out[OADUR_OFF + i] = (x < xlv[b]) ? log1pf((float)cnt) : 0.f;
    }
}

// -------------------- launch (single stream) -------------------------------------
extern "C" void kernel_launch(void* const* d_in, const int* in_sizes, int n_in,
                              void* d_out, int out_size)
{
    const float* om   = (const float*)d_in[0];
    const float* ols  = (const float*)d_in[1];
    const float* odur = (const float*)d_in[2];
    const float* z    = (const float*)d_in[3];
    const int*   xlen = (const int*)  d_in[4];
    const int*   ylen = (const int*)  d_in[5];
    float* out = (float*)d_out;

    prepx_kernel<<<(Bn*TXn + 255)/256, 256>>>(om, ols, odur, out);
    prepz_kernel<<<(Bn*Cc*TYn + 255)/256, 256>>>(z, ylen, out);
    fused_kernel<<<32 + NYT*Bn*4, 512>>>(xlen, ylen);   // 32 DP + 2048 gemm blocks
    bwd_kernel<<<Bn, 32>>>(xlen, ylen);
    tail_kernel<<<TB_ATTN + TB_GATH + TB_DUR, 256>>>(om, ols, xlen, ylen, out);
}

// round 15
// speedup vs baseline: 1.6598x; 1.6598x over previous
#include <cuda_runtime.h>
#include <cuda_bf16.h>
#include <math.h>
#include <stdint.h>

// Problem constants
#define Bn  32
#define Cc  80
#define TXn 512
#define TYn 2048
#define K2  160          // stacked K: [scale(80); mean*scale(80)]
#define NEGV (-1e9f)
#define LOG2PI 1.8378770664093453f
#define NYT (TYn/128)    // 16 y-tiles of 128 columns

// Output layout (flat f32, reference return order)
#define Z_OFF        0
#define YMEAN_OFF    (Bn*Cc*TYn)
#define YLOG_OFF     (2*Bn*Cc*TYn)
#define ATTN_OFF     (3*Bn*Cc*TYn)
#define ODUR_OFF     (ATTN_OFF + Bn*TYn*TXn)
#define OADUR_OFF    (ODUR_OFF + Bn*TXn)

// tail kernel block ranges (256 threads each)
#define TB_ATTN   (Bn*TYn/2)                  // 32768 blocks, 2 attn rows each
#define TB_GATH   (Bn*Cc*TYn/256)             // 20480 blocks
#define TB_DUR    (Bn*TXn/256)                // 64 blocks

// -------------------- scratch (__device__ globals) --------------------------
__device__ float    g_W[Bn*K2*TXn];              // [b][k][x]
__device__ float    g_Z[Bn*K2*TYn];              // [b][k][y]
__device__ float    g_rowA[Bn*TXn];              // logp1+logp4 per (b,x)
__device__ float    g_logpT[(size_t)Bn*TYn*TXn]; // 134 MB [b][y][x]
__device__ unsigned g_dbits[(size_t)Bn*TYn*16];  // dir bits, 32 per warp-word
__device__ int      g_xy[Bn*TYn];                // alignment index per (b,y)
__device__ int      g_prog[Bn*NYT];              // gemm tiles done per (b,ytile)

// -------------------- K1: per-(b,x) prep -------------------------------------
__global__ void prepx_kernel(const float* __restrict__ om,
                             const float* __restrict__ ols,
                             const float* __restrict__ odur,
                             float* __restrict__ out)
{
    int i = blockIdx.x * blockDim.x + threadIdx.x;
    if (i >= Bn*TXn) return;
    if (i < Bn*NYT) g_prog[i] = 0;     // reset producer counters each launch
    int b = i / TXn, x = i % TXn;
    const float* omb = om  + (size_t)b*Cc*TXn + x;
    const float* olb = ols + (size_t)b*Cc*TXn + x;
    float* wS = g_W + (size_t)b*K2*TXn + x;
    float sa = 0.f;
    #pragma unroll 4
    for (int c = 0; c < Cc; c++) {
        float l  = olb[(size_t)c*TXn];
        float sc = expf(-2.f*l);
        float m  = omb[(size_t)c*TXn];
        wS[(size_t)c*TXn]        = sc;
        wS[(size_t)(Cc+c)*TXn]   = m*sc;
        sa += -0.5f*LOG2PI - l - 0.5f*m*m*sc;
    }
    g_rowA[i] = sa;
    out[ODUR_OFF + i] = odur[i];
}

// -------------------- K2: z masking + Z matrix --------------------------------
__global__ void prepz_kernel(const float* __restrict__ z,
                             const int* __restrict__ yl,
                             float* __restrict__ out)
{
    int i = blockIdx.x * blockDim.x + threadIdx.x;
    if (i >= Bn*Cc*TYn) return;
    int b = i / (Cc*TYn);
    int r = i % (Cc*TYn);
    int c = r / TYn;
    int y = r % TYn;
    float zv = z[i];
    if (y >= yl[b]) zv = 0.f;
    out[Z_OFF + i] = zv;
    size_t zb = (size_t)b*K2*TYn;
    g_Z[zb + (size_t)c*TYn + y]      = -0.5f*zv*zv;
    g_Z[zb + (size_t)(Cc+c)*TYn + y] = zv;
}

// -------------------- K3: fused gemm (producers) + forward DP (consumers) ------
// (verbatim from the committed R13/R12 winner — DP body frozen)
__global__ void __launch_bounds__(512)
fused_kernel(const int* __restrict__ xl, const int* __restrict__ yl)
{
    __shared__ float smem[2*16*128];       // gemm tiles (fwd uses tiny slice)
    int tid = threadIdx.x;

    if (blockIdx.x >= 32) {
        // ---------------- GEMM producer role ----------------
        int gid = blockIdx.x - 32;
        int yt  = gid >> 7;                // 0..15 (slab-major)
        int rem = gid & 127;
        int b   = rem >> 2;
        int x0  = (rem & 3) * 128;
        int y0  = yt * 128;
        int xlen = xl[b], ylen = yl[b];

        bool skip = (x0 >= xlen) || (y0 >= ylen) ||
                    (x0 > y0 + 127) || (x0 + 127 < y0 - (ylen - xlen));
        if (!skip) {
            float (*zs)[128] = (float (*)[128])smem;
            float (*ws)[128] = (float (*)[128])(smem + 16*128);
            int lrow = tid >> 5;           // 0..15
            int lcol = (tid & 31) << 2;    // 0..124
            int ty   = tid >> 4;           // 0..31 (4 y each)
            int tx   = tid & 15;           // 0..15 (8 x each)

            const float* Zb = g_Z + (size_t)b*K2*TYn;
            const float* Wb = g_W + (size_t)b*K2*TXn;

            float acc[4][8] = {};
            for (int k0 = 0; k0 < K2; k0 += 16) {
                *(float4*)&zs[lrow][lcol] =
                    *(const float4*)&Zb[(size_t)(k0+lrow)*TYn + y0 + lcol];
                *(float4*)&ws[lrow][lcol] =
                    *(const float4*)&Wb[(size_t)(k0+lrow)*TXn + x0 + lcol];
                __syncthreads();
                #pragma unroll
                for (int k = 0; k < 16; k++) {
                    float4 zf = *(float4*)&zs[k][ty<<2];
                    float4 w0 = *(float4*)&ws[k][tx<<3];
                    float4 w1 = *(float4*)&ws[k][(tx<<3)+4];
                    float za[4] = {zf.x, zf.y, zf.z, zf.w};
                    float wa[8] = {w0.x,w0.y,w0.z,w0.w,w1.x,w1.y,w1.z,w1.w};
                    #pragma unroll
                    for (int i = 0; i < 4; i++)
                        #pragma unroll
                        for (int j = 0; j < 8; j++)
                            acc[i][j] += za[i]*wa[j];
                }
                __syncthreads();
            }

            float ra[8];
            #pragma unroll
            for (int j = 0; j < 8; j++)
                ra[j] = g_rowA[b*TXn + x0 + (tx<<3) + j];

            #pragma unroll
            for (int i = 0; i < 4; i++) {
                int y = y0 + (ty<<2) + i;
                float* op = g_logpT + ((size_t)b*TYn + y)*TXn + x0 + (tx<<3);
                float4 o0, o1;
                float* p0 = (float*)&o0; float* p1 = (float*)&o1;
                bool yok = (y < ylen);
                #pragma unroll
                for (int j = 0; j < 4; j++) {
                    int xa = x0 + (tx<<3) + j;
                    int xb = xa + 4;
                    p0[j] = (yok && xa < xlen) ? (acc[i][j]   + ra[j])   : 0.f;
                    p1[j] = (yok && xb < xlen) ? (acc[i][j+4] + ra[j+4]) : 0.f;
                }
                *(float4*)op       = o0;
                *(float4*)(op + 4) = o1;
            }
        }
        __threadfence();
        __syncthreads();
        if (tid == 0) atomicAdd(&g_prog[b*NYT + yt], 1);
        return;
    }

    // ---------------- forward-DP consumer role (R3 body + gating) ----------------
    int b    = blockIdx.x;
    int x    = tid;
    int w    = x >> 5, lane = x & 31;
    int xlen = xl[b], ylen = yl[b];

    float* sb = smem;                     // [2][16] boundary values

    unsigned force;
    {
        int rel = xlen - (w << 5);
        if (rel <= 0)      force = 0xFFFFFFFFu;
        else if (rel < 32) force = 0xFFFFFFFFu << rel;
        else               force = 0u;
    }

    float v = 0.f;
    if (lane == 31) { sb[0*16 + w] = 0.f; sb[1*16 + w] = 0.f; }

    const float* base  = g_logpT + (size_t)b*TYn*TXn + x;
    unsigned*    dbase = g_dbits + (size_t)b*TYn*16 + w;

    int last_yt = (ylen - 1) >> 7;

    auto gate = [&](int yt) {
        if (yt > last_yt) yt = last_yt;
        if (tid == 0) {
            const int* p = &g_prog[b*NYT + yt];
            int pv;
            do {
                asm volatile("ld.acquire.gpu.s32 %0, [%1];"
                             : "=r"(pv) : "l"(p) : "memory");
                if (pv < 4) __nanosleep(256);
            } while (pv < 4);
        }
        __syncthreads();
    };

    gate(0);

    const int PF = 8;
    float c[PF];
    #pragma unroll
    for (int d = 0; d < PF; d++)
        c[d] = (d < ylen) ? base[(size_t)d*TXn] : 0.f;
    __syncthreads();

    for (int j0 = 0; j0 < ylen; j0 += PF) {
        if ((j0 & 127) == 120) gate((j0 >> 7) + 1);

        float cn[PF];
        #pragma unroll
        for (int d = 0; d < PF; d++) {
            int j = j0 + d;
            if (j < ylen) {                      // uniform per block
                int jp = j + PF;
                cn[d] = (jp < ylen) ? base[(size_t)jp*TXn] : 0.f;

                float left = __shfl_up_sync(0xFFFFFFFFu, v, 1);
                if (lane == 0) left = (w == 0) ? NEGV : sb[(j & 1)*16 + (w - 1)];

                bool  di = v >= left;
                float nv = (di ? v : left) + c[d];
                if (x > j) nv = NEGV;

                unsigned bits = __ballot_sync(0xFFFFFFFFu, di) | force;
                if (lane == 0) dbase[(size_t)j*16] = bits;

                v = nv;
                if (lane == 31) sb[((j + 1) & 1)*16 + w] = nv;
                __syncthreads();
            }
        }
        #pragma unroll
        for (int d = 0; d < PF; d++) c[d] = cn[d];
    }
}

// -------------------- K4: backtrack (1 warp per batch, minimal chain) ----------
// (measured 74 us in R14; correctness-verified)
__global__ void __launch_bounds__(32)
bwd_kernel(const int* __restrict__ xl, const int* __restrict__ yl)
{
    int b = blockIdx.x, lane = threadIdx.x;
    int xlen = xl[b], ylen = yl[b];

    for (int j = ylen + lane; j < TYn; j += 32) g_xy[b*TYn + j] = 0;

    int idx = xlen - 1;
    for (int jhi = ylen - 1; jhi >= 0; jhi -= 32) {
        int steps = min(32, jhi + 1);
        int j = jhi - lane;
        int w0 = idx >> 5;                 // block-entry word; spans {w0, w0-1}
        unsigned d0 = 0xFFFFFFFFu, d1 = 0xFFFFFFFFu;
        if (lane < steps) {
            const unsigned* p = g_dbits + ((size_t)b*TYn + j)*16;
            d0 = p[w0];
            if (w0 >= 1) d1 = p[w0-1];
        }
        int myidx = 0;
        #pragma unroll 4
        for (int s = 0; s < steps; s++) {
            unsigned e0 = __shfl_sync(0xFFFFFFFFu, d0, s);
            unsigned e1 = __shfl_sync(0xFFFFFFFFu, d1, s);
            if (lane == s) myidx = idx;
            unsigned word = ((idx >> 5) == w0) ? e0 : e1;
            idx += (int)((word >> (idx & 31)) & 1u) - 1;
        }
        if (lane < steps) g_xy[b*TYn + jhi - lane] = myidx;
    }
}

// -------------------- K5: merged tail (attn + gathers + durations) -------------
__global__ void __launch_bounds__(256)
tail_kernel(const float* __restrict__ om,
            const float* __restrict__ ols,
            const int* __restrict__ xlv,
            const int* __restrict__ ylv,
            float* __restrict__ out)
{
    int blk = blockIdx.x;
    int tid = threadIdx.x;

    if (blk < TB_ATTN) {
        // attn_out: 2 rows per block, 128 threads each, float4 stores
        int r = (blk << 1) + (tid >> 7);      // row id in [0, Bn*TYn)
        int b = r >> 11;                      // TYn = 2048
        int y = r & (TYn - 1);
        int t = tid & 127;
        int xi = (y < ylv[b]) ? g_xy[b*TYn + y] : -1;
        int x4 = t << 2;
        float4 v = make_float4(0.f, 0.f, 0.f, 0.f);
        if (xi >= x4 && xi < x4 + 4) ((float*)&v)[xi - x4] = 1.0f;
        *(float4*)&out[ATTN_OFF + (size_t)r*TXn + x4] = v;
    } else if (blk < TB_ATTN + TB_GATH) {
        // y_mean / y_log_scale gathers
        int i = (blk - TB_ATTN)*256 + tid;
        int b = i / (Cc*TYn);
        int r = i % (Cc*TYn);
        int c = r / TYn;
        int y = r % TYn;
        float m = 0.f, s = 0.f;
        if (y < ylv[b]) {
            int x = g_xy[b*TYn + y];
            m = om [(size_t)(b*Cc + c)*TXn + x];
            s = ols[(size_t)(b*Cc + c)*TXn + x];
        }
        out[YMEAN_OFF + i] = m;
        out[YLOG_OFF  + i] = s;
    } else {
        // o_attn_dur: count via binary search over monotone xy[b][0..ylen)
        int i = (blk - TB_ATTN - TB_GATH)*256 + tid;
        int b = i / TXn, x = i % TXn;
        int ylen = ylv[b];
        const int* xy = g_xy + b*TYn;
        int lo = 0, hi = ylen;
        while (lo < hi) { int mid = (lo + hi) >> 1;
                          if (xy[mid] < x) lo = mid + 1; else hi = mid; }
        int lb = lo;
        lo = 0; hi = ylen;
        while (lo < hi) { int mid = (lo + hi) >> 1;
                          if (xy[mid] <= x) lo = mid + 1; else hi = mid; }
        int cnt = lo - lb;
        out[OADUR_OFF + i] = (x < xlv[b]) ? log1pf((float)cnt) : 0.f;
    }
}

// -------------------- launch (single stream) -------------------------------------
extern "C" void kernel_launch(void* const* d_in, const int* in_sizes, int n_in,
                              void* d_out, int out_size)
{
    const float* om   = (const float*)d_in[0];
    const float* ols  = (const float*)d_in[1];
    const float* odur = (const float*)d_in[2];
    const float* z    = (const float*)d_in[3];
    const int*   xlen = (const int*)  d_in[4];
    const int*   ylen = (const int*)  d_in[5];
    float* out = (float*)d_out;

    prepx_kernel<<<(Bn*TXn + 255)/256, 256>>>(om, ols, odur, out);
    prepz_kernel<<<(Bn*Cc*TYn + 255)/256, 256>>>(z, ylen, out);
    fused_kernel<<<32 + NYT*Bn*4, 512>>>(xlen, ylen);   // 32 DP + 2048 gemm blocks
    bwd_kernel<<<Bn, 32>>>(xlen, ylen);
    tail_kernel<<<TB_ATTN + TB_GATH + TB_DUR, 256>>>(om, ols, xlen, ylen, out);
}